// round 1
// baseline (speedup 1.0000x reference)
#include <cuda_runtime.h>
#include <cuda_bf16.h>
#include <math.h>

// Problem dims
#define BATCH 64
#define NCAPS 2048
#define IDIM 16
#define DOUT 256   // OUTPUT_CAPS * OUTPUT_DIM

// Scratch (static device globals: allowed; no cudaMalloc)
__device__ float g_u[(size_t)BATCH * NCAPS * DOUT];   // 134 MB
__device__ float g_C[(size_t)BATCH * DOUT * DOUT];    // 16 MB

// ---------------------------------------------------------------------------
// Stage 1: u[b,c,o] = sum_i x[b,c,i] * w[c,i,o]
// grid: 2048 (one CTA per capsule c), block: 256 (one thread per o)
// ---------------------------------------------------------------------------
__global__ void k_u(const float* __restrict__ x, const float* __restrict__ w) {
    const int c = blockIdx.x;
    const int o = threadIdx.x;

    __shared__ __align__(16) float Xs[BATCH * IDIM];   // 64 x 16

    float W[IDIM];
#pragma unroll
    for (int i = 0; i < IDIM; ++i)
        W[i] = w[((size_t)c * IDIM + i) * DOUT + o];   // coalesced over o

    for (int l = o; l < BATCH * IDIM; l += 256) {
        int bb = l >> 4, ii = l & 15;
        Xs[l] = x[((size_t)bb * NCAPS + c) * IDIM + ii];
    }
    __syncthreads();

    for (int bb = 0; bb < BATCH; ++bb) {
        const float4 x0 = *(const float4*)&Xs[bb * IDIM + 0];
        const float4 x1 = *(const float4*)&Xs[bb * IDIM + 4];
        const float4 x2 = *(const float4*)&Xs[bb * IDIM + 8];
        const float4 x3 = *(const float4*)&Xs[bb * IDIM + 12];
        float a0 = x0.x * W[0], a1 = x0.y * W[1], a2 = x0.z * W[2], a3 = x0.w * W[3];
        a0 = fmaf(x1.x, W[4], a0);  a1 = fmaf(x1.y, W[5], a1);
        a2 = fmaf(x1.z, W[6], a2);  a3 = fmaf(x1.w, W[7], a3);
        a0 = fmaf(x2.x, W[8], a0);  a1 = fmaf(x2.y, W[9], a1);
        a2 = fmaf(x2.z, W[10], a2); a3 = fmaf(x2.w, W[11], a3);
        a0 = fmaf(x3.x, W[12], a0); a1 = fmaf(x3.y, W[13], a1);
        a2 = fmaf(x3.z, W[14], a2); a3 = fmaf(x3.w, W[15], a3);
        g_u[((size_t)bb * NCAPS + c) * DOUT + o] = (a0 + a1) + (a2 + a3);
    }
}

// ---------------------------------------------------------------------------
// Stage 2: C_b = U_b^T U_b, symmetric: only 10 of 16 64x64 tiles computed.
// grid: (10, 64), block: 256 (16x16 thread grid, 4x4 microtile)
// ---------------------------------------------------------------------------
__global__ __launch_bounds__(256, 4) void k_syrk() {
    const int p = blockIdx.x;       // 0..9 triangular tile index
    const int b = blockIdx.y;

    int dt, et;
    if (p < 4)      { dt = 0; et = p; }
    else if (p < 7) { dt = 1; et = p - 3; }
    else if (p < 9) { dt = 2; et = p - 5; }
    else            { dt = 3; et = 3; }

    const int tid = threadIdx.x;
    const int tx = tid & 15, ty = tid >> 4;

    __shared__ __align__(16) float As[32][68];
    __shared__ __align__(16) float Bs[32][68];

    float acc[4][4];
#pragma unroll
    for (int i = 0; i < 4; ++i)
#pragma unroll
        for (int j = 0; j < 4; ++j) acc[i][j] = 0.0f;

    const float* Ub = g_u + (size_t)b * NCAPS * DOUT;
    const int dbase = dt * 64, ebase = et * 64;

    for (int kc = 0; kc < NCAPS; kc += 32) {
#pragma unroll
        for (int q = 0; q < 2; ++q) {
            int l = q * 256 + tid;          // 0..511
            int r = l >> 4;                 // 0..31
            int c4 = (l & 15) << 2;         // 0..60
            const float* src = Ub + (size_t)(kc + r) * DOUT;
            *(float4*)&As[r][c4] = *(const float4*)(src + dbase + c4);
            *(float4*)&Bs[r][c4] = *(const float4*)(src + ebase + c4);
        }
        __syncthreads();
#pragma unroll
        for (int kk = 0; kk < 32; ++kk) {
            float a0[4], b0[4];
            *(float4*)a0 = *(const float4*)&As[kk][ty << 2];
            *(float4*)b0 = *(const float4*)&Bs[kk][tx << 2];
#pragma unroll
            for (int i = 0; i < 4; ++i)
#pragma unroll
                for (int j = 0; j < 4; ++j)
                    acc[i][j] = fmaf(a0[i], b0[j], acc[i][j]);
        }
        __syncthreads();
    }

    float* Cb = g_C + (size_t)b * DOUT * DOUT;
#pragma unroll
    for (int i = 0; i < 4; ++i) {
#pragma unroll
        for (int j = 0; j < 4; ++j) {
            int d = dbase + (ty << 2) + i;
            int e = ebase + (tx << 2) + j;
            Cb[d * DOUT + e] = acc[i][j];
            if (dt != et) Cb[e * DOUT + d] = acc[i][j];
        }
    }
}

// ---------------------------------------------------------------------------
// Stage 3: top eigenvector of each C_b via Chebyshev-accelerated iteration.
// grid: 64, block: 256. C lower triangle in dynamic smem (131.6 KB).
// ---------------------------------------------------------------------------
#define TRI_N 32896                              // 256*257/2
#define EIG_SMEM_FLOATS (TRI_N + 3 * 256 + 64)
#define EIG_SMEM_BYTES (EIG_SMEM_FLOATS * 4)

__device__ __forceinline__ float warpSum(float v) {
#pragma unroll
    for (int o = 16; o; o >>= 1) v += __shfl_xor_sync(0xffffffffu, v, o);
    return v;
}

__device__ float blockSum(float val, float* red, int t) {
    val = warpSum(val);
    if ((t & 31) == 0) red[t >> 5] = val;
    __syncthreads();
    if (t < 32) {
        float x = (t < 8) ? red[t] : 0.0f;
        x = warpSum(x);
        if (t == 0) red[32] = x;
    }
    __syncthreads();
    float r = red[32];
    __syncthreads();
    return r;
}

__device__ float blockMax(float val, float* red, int t) {
#pragma unroll
    for (int o = 16; o; o >>= 1) val = fmaxf(val, __shfl_xor_sync(0xffffffffu, val, o));
    if ((t & 31) == 0) red[t >> 5] = val;
    __syncthreads();
    if (t < 32) {
        float x = (t < 8) ? red[t] : -1.0f;
#pragma unroll
        for (int o = 16; o; o >>= 1) x = fmaxf(x, __shfl_xor_sync(0xffffffffu, x, o));
        if (t == 0) red[32] = x;
    }
    __syncthreads();
    float r = red[32];
    __syncthreads();
    return r;
}

__device__ int blockMinInt(int val, float* redf, int t) {
    int* red = (int*)redf;
#pragma unroll
    for (int o = 16; o; o >>= 1) val = min(val, __shfl_xor_sync(0xffffffffu, val, o));
    if ((t & 31) == 0) red[t >> 5] = val;
    __syncthreads();
    if (t < 32) {
        int x = (t < 8) ? red[t] : 0x7fffffff;
#pragma unroll
        for (int o = 16; o; o >>= 1) x = min(x, __shfl_xor_sync(0xffffffffu, x, o));
        if (t == 0) red[32] = x;
    }
    __syncthreads();
    int r = red[32];
    __syncthreads();
    return r;
}

// y[t] = sum_j C[t][j] v[j], C stored as packed lower triangle in smem.
__device__ __forceinline__ float symMatvecRow(const float* __restrict__ tri,
                                              const float* __restrict__ v, int t) {
    float s0 = 0.f, s1 = 0.f, s2 = 0.f, s3 = 0.f;
    const int baseT = (t * (t + 1)) >> 1;
    int bj = 0;                       // bj = j0*(j0+1)/2, maintained incrementally
    for (int j0 = 0; j0 < 256; j0 += 4) {
        const float4 vj = *(const float4*)(v + j0);
        const int b0 = bj;
        const int b1 = b0 + j0 + 1;
        const int b2 = b1 + j0 + 2;
        const int b3 = b2 + j0 + 3;
        bj = b3 + j0 + 4;
        const int i0 = (j0 + 0 <= t) ? (baseT + j0 + 0) : (b0 + t);
        const int i1 = (j0 + 1 <= t) ? (baseT + j0 + 1) : (b1 + t);
        const int i2 = (j0 + 2 <= t) ? (baseT + j0 + 2) : (b2 + t);
        const int i3 = (j0 + 3 <= t) ? (baseT + j0 + 3) : (b3 + t);
        s0 = fmaf(tri[i0], vj.x, s0);
        s1 = fmaf(tri[i1], vj.y, s1);
        s2 = fmaf(tri[i2], vj.z, s2);
        s3 = fmaf(tri[i3], vj.w, s3);
    }
    return (s0 + s1) + (s2 + s3);
}

__global__ __launch_bounds__(256, 1) void k_eig(float* __restrict__ out) {
    extern __shared__ __align__(16) float sm[];
    float* tri = sm;               // 32896
    float* v   = sm + TRI_N;       // 256
    float* y   = v + 256;          // 256
    float* vp  = y + 256;          // 256
    float* red = vp + 256;         // 64 scratch

    const int b = blockIdx.x;
    const int t = threadIdx.x;
    const float* Cb = g_C + (size_t)b * DOUT * DOUT;

    // Load lower triangle (incl. diagonal), coalesced per row.
    for (int r = 0; r < 256; ++r) {
        if (t <= r) tri[((r * (r + 1)) >> 1) + t] = Cb[r * 256 + t];
    }
    __syncthreads();

    // init: v = C[:,0]
    v[t] = tri[(t * (t + 1)) >> 1];
    __syncthreads();
    {
        float n2 = blockSum(v[t] * v[t], red, t);
        v[t] *= rsqrtf(fmaxf(n2, 1e-30f));
    }
    __syncthreads();

    // Warm-up power iterations (seed Rayleigh quotient).
    for (int it = 0; it < 8; ++it) {
        float s = symMatvecRow(tri, v, t);
        float n2 = blockSum(s * s, red, t);   // internal syncs fence matvec reads
        v[t] = s * rsqrtf(fmaxf(n2, 1e-30f));
        __syncthreads();
    }

    // Chebyshev-accelerated iteration with residual-based convergence.
    for (int outer = 0; outer < 40; ++outer) {
        float s = symMatvecRow(tri, v, t);       // s = (C v)[t]
        float rho = blockSum(v[t] * s, red, t);  // Rayleigh quotient (v unit)
        float d = s - rho * v[t];
        float r2 = blockSum(d * d, red, t);
        float tol = 4e-6f * rho;
        if (r2 < tol * tol) break;               // uniform branch

        y[t] = s;
        const float inv2 = 2.0f / (rho * 0.9985f);
        __syncthreads();
        // T0 = v ; T1 = ((2/b)C - I) v
        vp[t] = v[t];
        v[t] = inv2 * y[t] - v[t];
        __syncthreads();
        for (int m = 0; m < 16; ++m) {
            float z = symMatvecRow(tri, v, t);
            __syncthreads();                      // all reads of v done
            float vn = 2.0f * inv2 * z - 2.0f * v[t] - vp[t];
            vp[t] = v[t];
            v[t] = vn;
            __syncthreads();
        }
        float n2 = blockSum(v[t] * v[t], red, t);
        v[t] *= rsqrtf(fmaxf(n2, 1e-30f));
        __syncthreads();
    }

    // Exact final normalization.
    {
        float n2 = blockSum(v[t] * v[t], red, t);
        v[t] *= (1.0f / sqrtf(fmaxf(n2, 1e-30f)));
        __syncthreads();
    }

    // Sign fix: make component with max |v| positive (first index on ties).
    float av = fabsf(v[t]);
    float mx = blockMax(av, red, t);
    int idx = (av == mx) ? t : 256;
    int imin = blockMinInt(idx, red, t);
    if (t == imin) red[40] = (v[t] < 0.0f) ? -1.0f : 1.0f;
    __syncthreads();
    out[b * 256 + t] = v[t] * red[40];
}

// ---------------------------------------------------------------------------
extern "C" void kernel_launch(void* const* d_in, const int* in_sizes, int n_in,
                              void* d_out, int out_size) {
    const float* x = (const float*)d_in[0];   // caps_output (64,2048,16)
    const float* w = (const float*)d_in[1];   // weights (2048,16,256)
    float* out = (float*)d_out;               // (64,256)

    cudaFuncSetAttribute(k_eig, cudaFuncAttributeMaxDynamicSharedMemorySize,
                         EIG_SMEM_BYTES);

    k_u<<<NCAPS, 256>>>(x, w);
    k_syrk<<<dim3(10, BATCH), 256>>>();
    k_eig<<<BATCH, 256, EIG_SMEM_BYTES>>>(out);
}

// round 4
// speedup vs baseline: 1.1100x; 1.1100x over previous
#include <cuda_runtime.h>
#include <cuda_bf16.h>
#include <cstdint>
#include <math.h>

// Problem dims
#define BATCH 64
#define NCAPS 2048
#define IDIM 16
#define DOUT 256   // OUTPUT_CAPS * OUTPUT_DIM

typedef unsigned int u32;
typedef unsigned long long u64;

// Scratch (static device globals: allowed; no cudaMalloc)
__device__ float g_u[(size_t)BATCH * NCAPS * DOUT];   // 134 MB
__device__ float g_C[(size_t)BATCH * DOUT * DOUT];    // 16 MB (lower triangle valid)

// ---------------------------------------------------------------------------
// Stage 1: u[b,c,o] = sum_i x[b,c,i] * w[c,i,o]
// grid: 2048 (one CTA per capsule c), block: 256 (one thread per o)
// ---------------------------------------------------------------------------
__global__ void k_u(const float* __restrict__ x, const float* __restrict__ w) {
    const int c = blockIdx.x;
    const int o = threadIdx.x;

    __shared__ __align__(16) float Xs[BATCH * IDIM];   // 64 x 16

    float W[IDIM];
#pragma unroll
    for (int i = 0; i < IDIM; ++i)
        W[i] = w[((size_t)c * IDIM + i) * DOUT + o];   // coalesced over o

    for (int l = o; l < BATCH * IDIM; l += 256) {
        int bb = l >> 4, ii = l & 15;
        Xs[l] = x[((size_t)bb * NCAPS + c) * IDIM + ii];
    }
    __syncthreads();

    for (int bb = 0; bb < BATCH; ++bb) {
        const float4 x0 = *(const float4*)&Xs[bb * IDIM + 0];
        const float4 x1 = *(const float4*)&Xs[bb * IDIM + 4];
        const float4 x2 = *(const float4*)&Xs[bb * IDIM + 8];
        const float4 x3 = *(const float4*)&Xs[bb * IDIM + 12];
        float a0 = x0.x * W[0], a1 = x0.y * W[1], a2 = x0.z * W[2], a3 = x0.w * W[3];
        a0 = fmaf(x1.x, W[4], a0);  a1 = fmaf(x1.y, W[5], a1);
        a2 = fmaf(x1.z, W[6], a2);  a3 = fmaf(x1.w, W[7], a3);
        a0 = fmaf(x2.x, W[8], a0);  a1 = fmaf(x2.y, W[9], a1);
        a2 = fmaf(x2.z, W[10], a2); a3 = fmaf(x2.w, W[11], a3);
        a0 = fmaf(x3.x, W[12], a0); a1 = fmaf(x3.y, W[13], a1);
        a2 = fmaf(x3.z, W[14], a2); a3 = fmaf(x3.w, W[15], a3);
        g_u[((size_t)bb * NCAPS + c) * DOUT + o] = (a0 + a1) + (a2 + a3);
    }
}

// ---------------------------------------------------------------------------
// Stage 2: lower-triangle tiles of C_b = U_b^T U_b.
// 64x64 tiles, dt >= et only (10 tiles). 64 threads, 8x8 microtile,
// packed fma.rn.f32x2 accumulators, cp.async double buffer.
// grid: (10, 64), block: 64
// ---------------------------------------------------------------------------
__device__ __forceinline__ void cp16(u32 saddr, const float* g) {
    asm volatile("cp.async.ca.shared.global [%0], [%1], 16;\n" :: "r"(saddr), "l"(g));
}
__device__ __forceinline__ u64 dupf(float f) {
    u64 r;
    asm("mov.b64 %0, {%1, %1};" : "=l"(r) : "f"(f));
    return r;
}
__device__ __forceinline__ void ffma2(u64& acc, u64 a, u64 b) {
    asm("fma.rn.f32x2 %0, %1, %2, %0;" : "+l"(acc) : "l"(a), "l"(b));
}

// load one 16x64 chunk of both tiles into buffer `buf`
__device__ __forceinline__ void sy_load(u32 sA, u32 sB,
                                        const float* Ub, int kc, int buf,
                                        int dbase, int ebase, bool diag, int tid) {
#pragma unroll
    for (int q = 0; q < 4; ++q) {
        int idx = q * 64 + tid;
        int r = idx >> 4;
        int c4 = (idx & 15) << 2;
        const float* srow = Ub + (size_t)(kc + r) * DOUT;
        u32 so = (u32)((buf * 1024 + r * 64 + c4) * 4);
        cp16(sA + so, srow + dbase + c4);
        if (!diag) cp16(sB + so, srow + ebase + c4);
    }
}

__global__ __launch_bounds__(64, 6) void k_syrk() {
    const int p = blockIdx.x;       // 0..9 triangular tile index, dt >= et
    const int b = blockIdx.y;

    int dt, et;
    if (p < 1)      { dt = 0; et = 0; }
    else if (p < 3) { dt = 1; et = p - 1; }
    else if (p < 6) { dt = 2; et = p - 3; }
    else            { dt = 3; et = p - 6; }
    const bool diag = (dt == et);

    const int tid = threadIdx.x;
    const int tx = tid & 7, ty = tid >> 3;

    __shared__ __align__(16) float As[2][16][64];
    __shared__ __align__(16) float Bs[2][16][64];

    const float* Ub = g_u + (size_t)b * NCAPS * DOUT;
    const int dbase = dt * 64, ebase = et * 64;

    u64 acc[4][8];
#pragma unroll
    for (int i = 0; i < 4; ++i)
#pragma unroll
        for (int j = 0; j < 8; ++j) acc[i][j] = 0ull;

    u32 sA = (u32)__cvta_generic_to_shared(&As[0][0][0]);
    u32 sB = (u32)__cvta_generic_to_shared(&Bs[0][0][0]);

    sy_load(sA, sB, Ub, 0, 0, dbase, ebase, diag, tid);
    asm volatile("cp.async.commit_group;\n");

    for (int chunk = 0; chunk < NCAPS / 16; ++chunk) {
        const int buf = chunk & 1;
        if (chunk + 1 < NCAPS / 16) {
            sy_load(sA, sB, Ub, (chunk + 1) * 16, buf ^ 1, dbase, ebase, diag, tid);
            asm volatile("cp.async.commit_group;\n");
            asm volatile("cp.async.wait_group 1;\n");
        } else {
            asm volatile("cp.async.wait_group 0;\n");
        }
        __syncthreads();

#pragma unroll
        for (int kk = 0; kk < 16; ++kk) {
            ulonglong2 a01 = *(const ulonglong2*)&As[buf][kk][ty * 8];
            ulonglong2 a23 = *(const ulonglong2*)&As[buf][kk][ty * 8 + 4];
            const float* bp = diag ? &As[buf][kk][tx * 8] : &Bs[buf][kk][tx * 8];
            float4 bl = *(const float4*)bp;
            float4 bh = *(const float4*)(bp + 4);
            u64 bd[8];
            bd[0] = dupf(bl.x); bd[1] = dupf(bl.y); bd[2] = dupf(bl.z); bd[3] = dupf(bl.w);
            bd[4] = dupf(bh.x); bd[5] = dupf(bh.y); bd[6] = dupf(bh.z); bd[7] = dupf(bh.w);
            u64 ap[4] = {a01.x, a01.y, a23.x, a23.y};
#pragma unroll
            for (int ip = 0; ip < 4; ++ip)
#pragma unroll
                for (int j = 0; j < 8; ++j)
                    ffma2(acc[ip][j], ap[ip], bd[j]);
        }
        __syncthreads();
    }

    // Epilogue: only the (d,e) placement (global lower triangle); no mirror.
    float* Cb = g_C + (size_t)b * DOUT * DOUT;
#pragma unroll
    for (int ip = 0; ip < 4; ++ip) {
        int d0 = dbase + ty * 8 + 2 * ip;
#pragma unroll
        for (int j = 0; j < 8; ++j) {
            float2 val = *(float2*)&acc[ip][j];
            int e = ebase + tx * 8 + j;
            Cb[d0 * DOUT + e] = val.x;
            Cb[(d0 + 1) * DOUT + e] = val.y;
        }
    }
}

// ---------------------------------------------------------------------------
// Stage 3: top eigenvector via Chebyshev iteration, adaptive spectral bound.
// C lower triangle in smem, rows 16B-padded: rowOff(4m+k) = 8m^2+8m+k(4m+4).
// ---------------------------------------------------------------------------
#define TRI_P 33280                              // padded triangle floats
#define EIG_SMEM_FLOATS (TRI_P + 2 * 256 + 64)
#define EIG_SMEM_BYTES (EIG_SMEM_FLOATS * 4)

__device__ __forceinline__ int rowOff(int r) {
    int m = r >> 2, k = r & 3;
    return 8 * m * m + 8 * m + k * (4 * m + 4);
}

__device__ __forceinline__ float warpSum(float v) {
#pragma unroll
    for (int o = 16; o; o >>= 1) v += __shfl_xor_sync(0xffffffffu, v, o);
    return v;
}

__device__ float blockSum(float val, float* red, int t) {
    val = warpSum(val);
    if ((t & 31) == 0) red[t >> 5] = val;
    __syncthreads();
    if (t < 32) {
        float x = (t < 8) ? red[t] : 0.0f;
        x = warpSum(x);
        if (t == 0) red[32] = x;
    }
    __syncthreads();
    float r = red[32];
    __syncthreads();
    return r;
}

__device__ float blockMax(float val, float* red, int t) {
#pragma unroll
    for (int o = 16; o; o >>= 1) val = fmaxf(val, __shfl_xor_sync(0xffffffffu, val, o));
    if ((t & 31) == 0) red[t >> 5] = val;
    __syncthreads();
    if (t < 32) {
        float x = (t < 8) ? red[t] : -1.0f;
#pragma unroll
        for (int o = 16; o; o >>= 1) x = fmaxf(x, __shfl_xor_sync(0xffffffffu, x, o));
        if (t == 0) red[32] = x;
    }
    __syncthreads();
    float r = red[32];
    __syncthreads();
    return r;
}

__device__ int blockMinInt(int val, float* redf, int t) {
    int* red = (int*)redf;
#pragma unroll
    for (int o = 16; o; o >>= 1) val = min(val, __shfl_xor_sync(0xffffffffu, val, o));
    if ((t & 31) == 0) red[t >> 5] = val;
    __syncthreads();
    if (t < 32) {
        int x = (t < 8) ? red[t] : 0x7fffffff;
#pragma unroll
        for (int o = 16; o; o >>= 1) x = min(x, __shfl_xor_sync(0xffffffffu, x, o));
        if (t == 0) red[32] = x;
    }
    __syncthreads();
    int r = red[32];
    __syncthreads();
    return r;
}

// y[t] = sum_j C[t][j] v[j]. Row part (j<=t): packed f32x2 over contiguous,
// zero-padded row t. Column part (j>t): conflict-free strided walk.
__device__ __forceinline__ float symMatvecRow(const float* __restrict__ tri,
                                              const float* __restrict__ v,
                                              int t, int rowT) {
    u64 acc0 = 0ull, acc1 = 0ull;
    const int nA = (t + 4) >> 2;
#pragma unroll 4
    for (int q = 0; q < nA; ++q) {
        ulonglong2 a = *(const ulonglong2*)(tri + rowT + 4 * q);
        ulonglong2 b = *(const ulonglong2*)(v + 4 * q);
        ffma2(acc0, a.x, b.x);
        ffma2(acc1, a.y, b.y);
    }
    float2 f0 = *(float2*)&acc0, f1 = *(float2*)&acc1;
    float s = (f0.x + f0.y) + (f1.x + f1.y);

    int j = t + 1;
    while ((j & 3) && j < 256) {       // at most 3 scalar steps to alignment
        s = fmaf(tri[rowOff(j) + t], v[j], s);
        ++j;
    }
    float s0 = 0.f, s1 = 0.f, s2 = 0.f, s3 = 0.f;
#pragma unroll 4
    for (int m = j >> 2; m < 64; ++m) {
        int base = 8 * m * m + 8 * m + t;
        int step = 4 * m + 4;
        float4 vj = *(const float4*)(v + 4 * m);
        s0 = fmaf(tri[base],            vj.x, s0);
        s1 = fmaf(tri[base + step],     vj.y, s1);
        s2 = fmaf(tri[base + 2 * step], vj.z, s2);
        s3 = fmaf(tri[base + 3 * step], vj.w, s3);
    }
    return s + ((s0 + s1) + (s2 + s3));
}

__global__ __launch_bounds__(256, 1) void k_eig(float* __restrict__ out) {
    extern __shared__ __align__(16) float sm[];
    float* tri = sm;                 // TRI_P
    float* v   = sm + TRI_P;         // 256
    float* vp  = v + 256;            // 256
    float* red = vp + 256;           // 64 scratch

    const int b = blockIdx.x;
    const int t = threadIdx.x;
    const float* Cb = g_C + (size_t)b * DOUT * DOUT;
    const int rowT = rowOff(t);

    // Zero the padded triangle (padding must be 0 for the row-part overread).
    {
        float4 z4 = make_float4(0.f, 0.f, 0.f, 0.f);
        for (int i = t; i < TRI_P / 4; i += 256) ((float4*)tri)[i] = z4;
    }
    __syncthreads();

    // Load lower triangle (incl. diagonal), coalesced per row.
    {
        int off = 0;
#pragma unroll 4
        for (int r = 0; r < 256; ++r) {
            if (t <= r) tri[off + t] = Cb[r * 256 + t];
            off += (r + 4) & ~3;
        }
    }
    __syncthreads();

    // init: v = C[:,0] (column 0 = first entries of each row)
    v[t] = tri[rowT];
    __syncthreads();
    {
        float n2 = blockSum(v[t] * v[t], red, t);
        v[t] *= rsqrtf(fmaxf(n2, 1e-30f));
    }
    __syncthreads();

    // Warm-up power iterations (seed Rayleigh quotient).
    for (int it = 0; it < 6; ++it) {
        float s = symMatvecRow(tri, v, t, rowT);
        float n2 = blockSum(s * s, red, t);   // internal syncs fence matvec reads
        v[t] = s * rsqrtf(fmaxf(n2, 1e-30f));
        __syncthreads();
    }

    // Chebyshev-accelerated iteration, adaptive interval [0, (1-eps)*rho].
    float eps = 0.008f;
    float r2prev = 1e30f;
    for (int outer = 0; outer < 48; ++outer) {
        float s = symMatvecRow(tri, v, t, rowT);     // s = (C v)[t]
        float rho = blockSum(v[t] * s, red, t);      // Rayleigh quotient (v unit)
        float d = s - rho * v[t];
        float r2 = blockSum(d * d, red, t);
        float tol = 4e-6f * rho;
        if (r2 < tol * tol) break;                   // uniform branch
        if (r2 > 0.3f * r2prev) eps = fmaxf(eps * 0.45f, 3e-4f);  // plateau
        r2prev = r2;

        const float inv2 = 2.0f / (rho * (1.0f - eps));
        // T0 = v ; T1 = ((2/b)C - I) v   (s already = Cv, barrier was in blockSum)
        vp[t] = v[t];
        v[t] = inv2 * s - v[t];
        __syncthreads();
        for (int m = 0; m < 16; ++m) {
            float z = symMatvecRow(tri, v, t, rowT);
            __syncthreads();                          // all reads of v done
            float vn = 2.0f * inv2 * z - 2.0f * v[t] - vp[t];
            vp[t] = v[t];
            v[t] = vn;
            __syncthreads();
        }
        float n2 = blockSum(v[t] * v[t], red, t);
        v[t] *= rsqrtf(fmaxf(n2, 1e-30f));
        __syncthreads();
    }

    // Exact final normalization.
    {
        float n2 = blockSum(v[t] * v[t], red, t);
        v[t] *= (1.0f / sqrtf(fmaxf(n2, 1e-30f)));
        __syncthreads();
    }

    // Sign fix: make component with max |v| positive (first index on ties).
    float av = fabsf(v[t]);
    float mx = blockMax(av, red, t);
    int idx = (av == mx) ? t : 256;
    int imin = blockMinInt(idx, red, t);
    if (t == imin) red[40] = (v[t] < 0.0f) ? -1.0f : 1.0f;
    __syncthreads();
    out[b * 256 + t] = v[t] * red[40];
}

// ---------------------------------------------------------------------------
extern "C" void kernel_launch(void* const* d_in, const int* in_sizes, int n_in,
                              void* d_out, int out_size) {
    const float* x = (const float*)d_in[0];   // caps_output (64,2048,16)
    const float* w = (const float*)d_in[1];   // weights (2048,16,256)
    float* out = (float*)d_out;               // (64,256)

    cudaFuncSetAttribute(k_eig, cudaFuncAttributeMaxDynamicSharedMemorySize,
                         EIG_SMEM_BYTES);

    k_u<<<NCAPS, 256>>>(x, w);
    k_syrk<<<dim3(10, BATCH), 64>>>();
    k_eig<<<BATCH, 256, EIG_SMEM_BYTES>>>(out);
}

// round 6
// speedup vs baseline: 1.1142x; 1.0038x over previous
#include <cuda_runtime.h>
#include <cuda_bf16.h>
#include <cstdint>
#include <math.h>

#define BATCH 64
#define NCAPS 2048
#define IDIM 16
#define DOUT 256

typedef unsigned int u32;
typedef unsigned long long u64;

__device__ float g_u[(size_t)BATCH * NCAPS * DOUT];   // 134 MB
__device__ float g_C[(size_t)BATCH * DOUT * DOUT];    // 16 MB (lower triangle valid)

// ---------------------------------------------------------------------------
// Stage 1: u[b,c,o] = sum_i x[b,c,i] * w[c,i,o]
// ---------------------------------------------------------------------------
__global__ void k_u(const float* __restrict__ x, const float* __restrict__ w) {
    const int c = blockIdx.x;
    const int o = threadIdx.x;

    __shared__ __align__(16) float Xs[BATCH * IDIM];

    float W[IDIM];
#pragma unroll
    for (int i = 0; i < IDIM; ++i)
        W[i] = w[((size_t)c * IDIM + i) * DOUT + o];

    for (int l = o; l < BATCH * IDIM; l += 256) {
        int bb = l >> 4, ii = l & 15;
        Xs[l] = x[((size_t)bb * NCAPS + c) * IDIM + ii];
    }
    __syncthreads();

    for (int bb = 0; bb < BATCH; ++bb) {
        const float4 x0 = *(const float4*)&Xs[bb * IDIM + 0];
        const float4 x1 = *(const float4*)&Xs[bb * IDIM + 4];
        const float4 x2 = *(const float4*)&Xs[bb * IDIM + 8];
        const float4 x3 = *(const float4*)&Xs[bb * IDIM + 12];
        float a0 = x0.x * W[0], a1 = x0.y * W[1], a2 = x0.z * W[2], a3 = x0.w * W[3];
        a0 = fmaf(x1.x, W[4], a0);  a1 = fmaf(x1.y, W[5], a1);
        a2 = fmaf(x1.z, W[6], a2);  a3 = fmaf(x1.w, W[7], a3);
        a0 = fmaf(x2.x, W[8], a0);  a1 = fmaf(x2.y, W[9], a1);
        a2 = fmaf(x2.z, W[10], a2); a3 = fmaf(x2.w, W[11], a3);
        a0 = fmaf(x3.x, W[12], a0); a1 = fmaf(x3.y, W[13], a1);
        a2 = fmaf(x3.z, W[14], a2); a3 = fmaf(x3.w, W[15], a3);
        g_u[((size_t)bb * NCAPS + c) * DOUT + o] = (a0 + a1) + (a2 + a3);
    }
}

// ---------------------------------------------------------------------------
// Stage 2: lower-triangle tiles of C_b = U_b^T U_b (FFMA2, cp.async dbuf)
// grid: (10, 64), block: 64
// ---------------------------------------------------------------------------
__device__ __forceinline__ void cp16(u32 saddr, const float* g) {
    asm volatile("cp.async.ca.shared.global [%0], [%1], 16;\n" :: "r"(saddr), "l"(g));
}
__device__ __forceinline__ u64 dupf(float f) {
    u64 r;
    asm("mov.b64 %0, {%1, %1};" : "=l"(r) : "f"(f));
    return r;
}
__device__ __forceinline__ void ffma2(u64& acc, u64 a, u64 b) {
    asm("fma.rn.f32x2 %0, %1, %2, %0;" : "+l"(acc) : "l"(a), "l"(b));
}

__device__ __forceinline__ void sy_load(u32 sA, u32 sB,
                                        const float* Ub, int kc, int buf,
                                        int dbase, int ebase, bool diag, int tid) {
#pragma unroll
    for (int q = 0; q < 4; ++q) {
        int idx = q * 64 + tid;
        int r = idx >> 4;
        int c4 = (idx & 15) << 2;
        const float* srow = Ub + (size_t)(kc + r) * DOUT;
        u32 so = (u32)((buf * 1024 + r * 64 + c4) * 4);
        cp16(sA + so, srow + dbase + c4);
        if (!diag) cp16(sB + so, srow + ebase + c4);
    }
}

__global__ __launch_bounds__(64, 6) void k_syrk() {
    const int p = blockIdx.x;
    const int b = blockIdx.y;

    int dt, et;
    if (p < 1)      { dt = 0; et = 0; }
    else if (p < 3) { dt = 1; et = p - 1; }
    else if (p < 6) { dt = 2; et = p - 3; }
    else            { dt = 3; et = p - 6; }
    const bool diag = (dt == et);

    const int tid = threadIdx.x;
    const int tx = tid & 7, ty = tid >> 3;

    __shared__ __align__(16) float As[2][16][64];
    __shared__ __align__(16) float Bs[2][16][64];

    const float* Ub = g_u + (size_t)b * NCAPS * DOUT;
    const int dbase = dt * 64, ebase = et * 64;

    u64 acc[4][8];
#pragma unroll
    for (int i = 0; i < 4; ++i)
#pragma unroll
        for (int j = 0; j < 8; ++j) acc[i][j] = 0ull;

    u32 sA = (u32)__cvta_generic_to_shared(&As[0][0][0]);
    u32 sB = (u32)__cvta_generic_to_shared(&Bs[0][0][0]);

    sy_load(sA, sB, Ub, 0, 0, dbase, ebase, diag, tid);
    asm volatile("cp.async.commit_group;\n");

    for (int chunk = 0; chunk < NCAPS / 16; ++chunk) {
        const int buf = chunk & 1;
        if (chunk + 1 < NCAPS / 16) {
            sy_load(sA, sB, Ub, (chunk + 1) * 16, buf ^ 1, dbase, ebase, diag, tid);
            asm volatile("cp.async.commit_group;\n");
            asm volatile("cp.async.wait_group 1;\n");
        } else {
            asm volatile("cp.async.wait_group 0;\n");
        }
        __syncthreads();

#pragma unroll
        for (int kk = 0; kk < 16; ++kk) {
            ulonglong2 a01 = *(const ulonglong2*)&As[buf][kk][ty * 8];
            ulonglong2 a23 = *(const ulonglong2*)&As[buf][kk][ty * 8 + 4];
            const float* bp = diag ? &As[buf][kk][tx * 8] : &Bs[buf][kk][tx * 8];
            float4 bl = *(const float4*)bp;
            float4 bh = *(const float4*)(bp + 4);
            u64 bd[8];
            bd[0] = dupf(bl.x); bd[1] = dupf(bl.y); bd[2] = dupf(bl.z); bd[3] = dupf(bl.w);
            bd[4] = dupf(bh.x); bd[5] = dupf(bh.y); bd[6] = dupf(bh.z); bd[7] = dupf(bh.w);
            u64 ap[4] = {a01.x, a01.y, a23.x, a23.y};
#pragma unroll
            for (int ip = 0; ip < 4; ++ip)
#pragma unroll
                for (int j = 0; j < 8; ++j)
                    ffma2(acc[ip][j], ap[ip], bd[j]);
        }
        __syncthreads();
    }

    float* Cb = g_C + (size_t)b * DOUT * DOUT;
#pragma unroll
    for (int ip = 0; ip < 4; ++ip) {
        int d0 = dbase + ty * 8 + 2 * ip;
#pragma unroll
        for (int j = 0; j < 8; ++j) {
            float2 val = *(float2*)&acc[ip][j];
            int e = ebase + tx * 8 + j;
            Cb[d0 * DOUT + e] = val.x;
            Cb[(d0 + 1) * DOUT + e] = val.y;
        }
    }
}

// ---------------------------------------------------------------------------
// Stage 3: top eigenvector via Chebyshev; two-pass all-vector matvec.
// C lower triangle packed, rows 16B-padded: rowOff(4m+k) = 8m^2+8m+k(4m+4).
// ---------------------------------------------------------------------------
#define TRI_P 33280
#define Y2S_STRIDE 264
#define EIG_SMEM_FLOATS (TRI_P + 2 * 256 + 64 + 8 * Y2S_STRIDE)
#define EIG_SMEM_BYTES (EIG_SMEM_FLOATS * 4)

__device__ __forceinline__ int rowOff(int r) {
    int m = r >> 2, k = r & 3;
    return 8 * m * m + 8 * m + k * (4 * m + 4);
}

__device__ __forceinline__ float warpSum(float v) {
#pragma unroll
    for (int o = 16; o; o >>= 1) v += __shfl_xor_sync(0xffffffffu, v, o);
    return v;
}
__device__ float blockSum(float val, float* red, int t) {
    val = warpSum(val);
    if ((t & 31) == 0) red[t >> 5] = val;
    __syncthreads();
    if (t < 32) {
        float x = (t < 8) ? red[t] : 0.0f;
        x = warpSum(x);
        if (t == 0) red[32] = x;
    }
    __syncthreads();
    float r = red[32];
    __syncthreads();
    return r;
}
__device__ float blockMax(float val, float* red, int t) {
#pragma unroll
    for (int o = 16; o; o >>= 1) val = fmaxf(val, __shfl_xor_sync(0xffffffffu, val, o));
    if ((t & 31) == 0) red[t >> 5] = val;
    __syncthreads();
    if (t < 32) {
        float x = (t < 8) ? red[t] : -1.0f;
#pragma unroll
        for (int o = 16; o; o >>= 1) x = fmaxf(x, __shfl_xor_sync(0xffffffffu, x, o));
        if (t == 0) red[32] = x;
    }
    __syncthreads();
    float r = red[32];
    __syncthreads();
    return r;
}
__device__ int blockMinInt(int val, float* redf, int t) {
    int* red = (int*)redf;
#pragma unroll
    for (int o = 16; o; o >>= 1) val = min(val, __shfl_xor_sync(0xffffffffu, val, o));
    if ((t & 31) == 0) red[t >> 5] = val;
    __syncthreads();
    if (t < 32) {
        int x = (t < 8) ? red[t] : 0x7fffffff;
#pragma unroll
        for (int o = 16; o; o >>= 1) x = min(x, __shfl_xor_sync(0xffffffffu, x, o));
        if (t == 0) red[32] = x;
    }
    __syncthreads();
    int r = red[32];
    __syncthreads();
    return r;
}

// y[t] = sum_j C[t][j] v[j]. Pass1: row t (j<=t, FFMA2 vector). Pass2: warp-
// cooperative scatter over rows (vector loads, register column accumulators).
// Contains ONE internal __syncthreads. Caller must sync after modifying v.
__device__ __forceinline__ float symMatvec2(const float* __restrict__ tri,
                                            const float* __restrict__ v,
                                            float* __restrict__ y2s,
                                            int t, int rowT) {
    const int l = t & 31, w = t >> 5;

    // pass 1
    u64 a0 = 0ull, a1 = 0ull;
    const int nA = (t + 4) >> 2;
#pragma unroll 4
    for (int q = 0; q < nA; ++q) {
        ulonglong2 A = *(const ulonglong2*)(tri + rowT + 4 * q);
        ulonglong2 B = *(const ulonglong2*)(v + 4 * q);
        ffma2(a0, A.x, B.x);
        ffma2(a1, A.y, B.y);
    }
    float2 f0 = *(float2*)&a0, f1 = *(float2*)&a1;
    float y1 = (f0.x + f0.y) + (f1.x + f1.y);

    // pass 2: rows j = 8*jj + w; lane l owns cols {4l..4l+3, 128+4l..128+4l+3}
    float ca0 = 0.f, ca1 = 0.f, ca2 = 0.f, ca3 = 0.f;
    float ca4 = 0.f, ca5 = 0.f, ca6 = 0.f, ca7 = 0.f;
    const int c0 = 4 * l;
#pragma unroll 4
    for (int jj = 0; jj < 32; ++jj) {
        int j = 8 * jj + w;
        int m = j >> 2, k = j & 3;
        int ro = 8 * m * m + 8 * m + k * (4 * m + 4);
        float vj = v[j];
        int L = (j & ~3) + 4;
        if (c0 < L) {
            float4 q4 = *(const float4*)(tri + ro + c0);
            ca0 = fmaf(q4.x, vj, ca0); ca1 = fmaf(q4.y, vj, ca1);
            ca2 = fmaf(q4.z, vj, ca2); ca3 = fmaf(q4.w, vj, ca3);
        }
        if (c0 + 128 < L) {
            float4 q4 = *(const float4*)(tri + ro + c0 + 128);
            ca4 = fmaf(q4.x, vj, ca4); ca5 = fmaf(q4.y, vj, ca5);
            ca6 = fmaf(q4.z, vj, ca6); ca7 = fmaf(q4.w, vj, ca7);
        }
    }
    *(float4*)&y2s[w * Y2S_STRIDE + c0] = make_float4(ca0, ca1, ca2, ca3);
    *(float4*)&y2s[w * Y2S_STRIDE + 128 + c0] = make_float4(ca4, ca5, ca6, ca7);
    __syncthreads();

    float y2 = 0.f;
#pragma unroll
    for (int ww = 0; ww < 8; ++ww) y2 += y2s[ww * Y2S_STRIDE + t];
    return y1 + y2 - tri[rowT + t] * v[t];
}

__global__ __launch_bounds__(256, 1) void k_eig(float* __restrict__ out) {
    extern __shared__ __align__(16) float sm[];
    float* tri = sm;                   // TRI_P
    float* v   = sm + TRI_P;           // 256
    float* vp  = v + 256;              // 256
    float* red = vp + 256;             // 64
    float* y2s = red + 64;             // 8 * 264

    const int b = blockIdx.x;
    const int t = threadIdx.x;
    const float* Cb = g_C + (size_t)b * DOUT * DOUT;
    const int rowT = rowOff(t);

    // zero padded triangle (padding must be 0)
    {
        float4 z4 = make_float4(0.f, 0.f, 0.f, 0.f);
        for (int i = t; i < TRI_P / 4; i += 256) ((float4*)tri)[i] = z4;
    }
    __syncthreads();

    // load lower triangle
    {
        int off = 0;
#pragma unroll 4
        for (int r = 0; r < 256; ++r) {
            if (t <= r) tri[off + t] = Cb[r * 256 + t];
            off += (r + 4) & ~3;
        }
    }
    __syncthreads();

    v[t] = tri[rowT];   // C[:,0]
    __syncthreads();
    {
        float n2 = blockSum(v[t] * v[t], red, t);
        v[t] *= rsqrtf(fmaxf(n2, 1e-30f));
    }
    __syncthreads();

    for (int it = 0; it < 6; ++it) {
        float s = symMatvec2(tri, v, y2s, t, rowT);
        float n2 = blockSum(s * s, red, t);
        v[t] = s * rsqrtf(fmaxf(n2, 1e-30f));
        __syncthreads();
    }

    float eps = 0.008f;
    float r2prev = 1e30f;
    for (int outer = 0; outer < 48; ++outer) {
        float s = symMatvec2(tri, v, y2s, t, rowT);
        float rho = blockSum(v[t] * s, red, t);
        float d = s - rho * v[t];
        float r2 = blockSum(d * d, red, t);
        float tol = 4e-6f * rho;
        if (r2 < tol * tol) break;
        if (r2 > 0.3f * r2prev) eps = fmaxf(eps * 0.45f, 3e-4f);
        r2prev = r2;

        const float inv2 = 2.0f / (rho * (1.0f - eps));
        vp[t] = v[t];
        v[t] = inv2 * s - v[t];
        __syncthreads();
        for (int m = 0; m < 16; ++m) {
            float z = symMatvec2(tri, v, y2s, t, rowT);
            float vn = 2.0f * inv2 * z - 2.0f * v[t] - vp[t];
            vp[t] = v[t];
            v[t] = vn;
            __syncthreads();
        }
        float n2 = blockSum(v[t] * v[t], red, t);
        v[t] *= rsqrtf(fmaxf(n2, 1e-30f));
        __syncthreads();
    }

    {
        float n2 = blockSum(v[t] * v[t], red, t);
        v[t] *= (1.0f / sqrtf(fmaxf(n2, 1e-30f)));
        __syncthreads();
    }

    float av = fabsf(v[t]);
    float mx = blockMax(av, red, t);
    int idx = (av == mx) ? t : 256;
    int imin = blockMinInt(idx, red, t);
    if (t == imin) red[40] = (v[t] < 0.0f) ? -1.0f : 1.0f;
    __syncthreads();
    out[b * 256 + t] = v[t] * red[40];
}

// ---------------------------------------------------------------------------
extern "C" void kernel_launch(void* const* d_in, const int* in_sizes, int n_in,
                              void* d_out, int out_size) {
    const float* x = (const float*)d_in[0];
    const float* w = (const float*)d_in[1];
    float* out = (float*)d_out;

    cudaFuncSetAttribute(k_eig, cudaFuncAttributeMaxDynamicSharedMemorySize,
                         EIG_SMEM_BYTES);

    k_u<<<NCAPS, 256>>>(x, w);
    k_syrk<<<dim3(10, BATCH), 64>>>();
    k_eig<<<BATCH, 256, EIG_SMEM_BYTES>>>(out);
}

// round 7
// speedup vs baseline: 1.4688x; 1.3183x over previous
#include <cuda_runtime.h>
#include <cuda_bf16.h>
#include <cstdint>
#include <math.h>

#define BATCH 64
#define NCAPS 2048
#define IDIM 16
#define DOUT 256

typedef unsigned int u32;
typedef unsigned long long u64;

__device__ float g_u[(size_t)BATCH * NCAPS * DOUT];   // 134 MB
__device__ float g_C[(size_t)BATCH * DOUT * DOUT];    // 16 MB (lower triangle valid)

// ---------------------------------------------------------------------------
// Stage 1: u[b,c,o] = sum_i x[b,c,i] * w[c,i,o]
// ---------------------------------------------------------------------------
__global__ void k_u(const float* __restrict__ x, const float* __restrict__ w) {
    const int c = blockIdx.x;
    const int o = threadIdx.x;

    __shared__ __align__(16) float Xs[BATCH * IDIM];

    float W[IDIM];
#pragma unroll
    for (int i = 0; i < IDIM; ++i)
        W[i] = w[((size_t)c * IDIM + i) * DOUT + o];

    for (int l = o; l < BATCH * IDIM; l += 256) {
        int bb = l >> 4, ii = l & 15;
        Xs[l] = x[((size_t)bb * NCAPS + c) * IDIM + ii];
    }
    __syncthreads();

    for (int bb = 0; bb < BATCH; ++bb) {
        const float4 x0 = *(const float4*)&Xs[bb * IDIM + 0];
        const float4 x1 = *(const float4*)&Xs[bb * IDIM + 4];
        const float4 x2 = *(const float4*)&Xs[bb * IDIM + 8];
        const float4 x3 = *(const float4*)&Xs[bb * IDIM + 12];
        float a0 = x0.x * W[0], a1 = x0.y * W[1], a2 = x0.z * W[2], a3 = x0.w * W[3];
        a0 = fmaf(x1.x, W[4], a0);  a1 = fmaf(x1.y, W[5], a1);
        a2 = fmaf(x1.z, W[6], a2);  a3 = fmaf(x1.w, W[7], a3);
        a0 = fmaf(x2.x, W[8], a0);  a1 = fmaf(x2.y, W[9], a1);
        a2 = fmaf(x2.z, W[10], a2); a3 = fmaf(x2.w, W[11], a3);
        a0 = fmaf(x3.x, W[12], a0); a1 = fmaf(x3.y, W[13], a1);
        a2 = fmaf(x3.z, W[14], a2); a3 = fmaf(x3.w, W[15], a3);
        g_u[((size_t)bb * NCAPS + c) * DOUT + o] = (a0 + a1) + (a2 + a3);
    }
}

// ---------------------------------------------------------------------------
// Stage 2: lower-triangle tiles of C_b = U_b^T U_b (FFMA2, cp.async dbuf)
// grid: (10, 64), block: 64  — unchanged from R4/R6
// ---------------------------------------------------------------------------
__device__ __forceinline__ void cp16(u32 saddr, const float* g) {
    asm volatile("cp.async.ca.shared.global [%0], [%1], 16;\n" :: "r"(saddr), "l"(g));
}
__device__ __forceinline__ u64 dupf(float f) {
    u64 r;
    asm("mov.b64 %0, {%1, %1};" : "=l"(r) : "f"(f));
    return r;
}
__device__ __forceinline__ void ffma2(u64& acc, u64 a, u64 b) {
    asm("fma.rn.f32x2 %0, %1, %2, %0;" : "+l"(acc) : "l"(a), "l"(b));
}

__device__ __forceinline__ void sy_load(u32 sA, u32 sB,
                                        const float* Ub, int kc, int buf,
                                        int dbase, int ebase, bool diag, int tid) {
#pragma unroll
    for (int q = 0; q < 4; ++q) {
        int idx = q * 64 + tid;
        int r = idx >> 4;
        int c4 = (idx & 15) << 2;
        const float* srow = Ub + (size_t)(kc + r) * DOUT;
        u32 so = (u32)((buf * 1024 + r * 64 + c4) * 4);
        cp16(sA + so, srow + dbase + c4);
        if (!diag) cp16(sB + so, srow + ebase + c4);
    }
}

__global__ __launch_bounds__(64, 6) void k_syrk() {
    const int p = blockIdx.x;
    const int b = blockIdx.y;

    int dt, et;
    if (p < 1)      { dt = 0; et = 0; }
    else if (p < 3) { dt = 1; et = p - 1; }
    else if (p < 6) { dt = 2; et = p - 3; }
    else            { dt = 3; et = p - 6; }
    const bool diag = (dt == et);

    const int tid = threadIdx.x;
    const int tx = tid & 7, ty = tid >> 3;

    __shared__ __align__(16) float As[2][16][64];
    __shared__ __align__(16) float Bs[2][16][64];

    const float* Ub = g_u + (size_t)b * NCAPS * DOUT;
    const int dbase = dt * 64, ebase = et * 64;

    u64 acc[4][8];
#pragma unroll
    for (int i = 0; i < 4; ++i)
#pragma unroll
        for (int j = 0; j < 8; ++j) acc[i][j] = 0ull;

    u32 sA = (u32)__cvta_generic_to_shared(&As[0][0][0]);
    u32 sB = (u32)__cvta_generic_to_shared(&Bs[0][0][0]);

    sy_load(sA, sB, Ub, 0, 0, dbase, ebase, diag, tid);
    asm volatile("cp.async.commit_group;\n");

    for (int chunk = 0; chunk < NCAPS / 16; ++chunk) {
        const int buf = chunk & 1;
        if (chunk + 1 < NCAPS / 16) {
            sy_load(sA, sB, Ub, (chunk + 1) * 16, buf ^ 1, dbase, ebase, diag, tid);
            asm volatile("cp.async.commit_group;\n");
            asm volatile("cp.async.wait_group 1;\n");
        } else {
            asm volatile("cp.async.wait_group 0;\n");
        }
        __syncthreads();

#pragma unroll
        for (int kk = 0; kk < 16; ++kk) {
            ulonglong2 a01 = *(const ulonglong2*)&As[buf][kk][ty * 8];
            ulonglong2 a23 = *(const ulonglong2*)&As[buf][kk][ty * 8 + 4];
            const float* bp = diag ? &As[buf][kk][tx * 8] : &Bs[buf][kk][tx * 8];
            float4 bl = *(const float4*)bp;
            float4 bh = *(const float4*)(bp + 4);
            u64 bd[8];
            bd[0] = dupf(bl.x); bd[1] = dupf(bl.y); bd[2] = dupf(bl.z); bd[3] = dupf(bl.w);
            bd[4] = dupf(bh.x); bd[5] = dupf(bh.y); bd[6] = dupf(bh.z); bd[7] = dupf(bh.w);
            u64 ap[4] = {a01.x, a01.y, a23.x, a23.y};
#pragma unroll
            for (int ip = 0; ip < 4; ++ip)
#pragma unroll
                for (int j = 0; j < 8; ++j)
                    ffma2(acc[ip][j], ap[ip], bd[j]);
        }
        __syncthreads();
    }

    float* Cb = g_C + (size_t)b * DOUT * DOUT;
#pragma unroll
    for (int ip = 0; ip < 4; ++ip) {
        int d0 = dbase + ty * 8 + 2 * ip;
#pragma unroll
        for (int j = 0; j < 8; ++j) {
            float2 val = *(float2*)&acc[ip][j];
            int e = ebase + tx * 8 + j;
            Cb[d0 * DOUT + e] = val.x;
            Cb[(d0 + 1) * DOUT + e] = val.y;
        }
    }
}

// ---------------------------------------------------------------------------
// Stage 3: top eigenvector via Chebyshev.
// C stored as 36 swizzled 32x32 blocks (lower block-triangle; diag mirrored).
// Matvec = 64 conflict-free pass-units (36 row + 28 col), 8 per warp.
// ---------------------------------------------------------------------------
#define NBLK 36
#define BLK_FLOATS 1024
#define Y2S_STRIDE 264
#define EIG_SMEM_FLOATS (NBLK * BLK_FLOATS + 2 * 256 + 64 + 8 * Y2S_STRIDE)
#define EIG_SMEM_BYTES (EIG_SMEM_FLOATS * 4)

// block s -> (R, C)
__device__ const unsigned char SB_R[NBLK] = {
    0, 1,1, 2,2,2, 3,3,3,3, 4,4,4,4,4, 5,5,5,5,5,5,
    6,6,6,6,6,6,6, 7,7,7,7,7,7,7,7 };
__device__ const unsigned char SB_C[NBLK] = {
    0, 0,1, 0,1,2, 0,1,2,3, 0,1,2,3,4, 0,1,2,3,4,5,
    0,1,2,3,4,5,6, 0,1,2,3,4,5,6,7 };

// pass-units: enc = R*32 + C*4 + type (type 0 = row-pass, 1 = col-pass)
__device__ const unsigned char UNITS[64] = {
    0, 32,33, 36, 64,65, 68,69, 72, 96,97, 100,101, 104,105, 108,
    128,129, 132,133, 136,137, 140,141, 144,
    160,161, 164,165, 168,169, 172,173, 176,177, 180,
    192,193, 196,197, 200,201, 204,205, 208,209, 212,213, 216,
    224,225, 228,229, 232,233, 236,237, 240,241, 244,245, 248,249, 252 };

// swizzled offset within a block: element (r, c)
__device__ __forceinline__ int sw_off(int r, int c) {
    return r * 32 + ((((c >> 2) ^ (r & 7)) << 2) | (c & 3));
}

__device__ __forceinline__ float warpSum(float v) {
#pragma unroll
    for (int o = 16; o; o >>= 1) v += __shfl_xor_sync(0xffffffffu, v, o);
    return v;
}
__device__ float blockSum(float val, float* red, int t) {
    val = warpSum(val);
    if ((t & 31) == 0) red[t >> 5] = val;
    __syncthreads();
    if (t < 32) {
        float x = (t < 8) ? red[t] : 0.0f;
        x = warpSum(x);
        if (t == 0) red[32] = x;
    }
    __syncthreads();
    float r = red[32];
    __syncthreads();
    return r;
}
__device__ float blockMax(float val, float* red, int t) {
#pragma unroll
    for (int o = 16; o; o >>= 1) val = fmaxf(val, __shfl_xor_sync(0xffffffffu, val, o));
    if ((t & 31) == 0) red[t >> 5] = val;
    __syncthreads();
    if (t < 32) {
        float x = (t < 8) ? red[t] : -1.0f;
#pragma unroll
        for (int o = 16; o; o >>= 1) x = fmaxf(x, __shfl_xor_sync(0xffffffffu, x, o));
        if (t == 0) red[32] = x;
    }
    __syncthreads();
    float r = red[32];
    __syncthreads();
    return r;
}
__device__ int blockMinInt(int val, float* redf, int t) {
    int* red = (int*)redf;
#pragma unroll
    for (int o = 16; o; o >>= 1) val = min(val, __shfl_xor_sync(0xffffffffu, val, o));
    if ((t & 31) == 0) red[t >> 5] = val;
    __syncthreads();
    if (t < 32) {
        int x = (t < 8) ? red[t] : 0x7fffffff;
#pragma unroll
        for (int o = 16; o; o >>= 1) x = min(x, __shfl_xor_sync(0xffffffffu, x, o));
        if (t == 0) red[32] = x;
    }
    __syncthreads();
    int r = red[32];
    __syncthreads();
    return r;
}

// y[t] = (C v)[t]. One internal __syncthreads. Caller syncs after updating v.
__device__ __forceinline__ float symMatvecB(const float* __restrict__ blocks,
                                            const float* __restrict__ v,
                                            float* __restrict__ y2s,
                                            int t) {
    const int l = t & 31, w = t >> 5;
    float* myp = y2s + w * Y2S_STRIDE;

    // zero my warp-private partial (safe: warp-private, caller-synced)
#pragma unroll
    for (int k = 0; k < 8; ++k) myp[32 * k + l] = 0.0f;

#pragma unroll 1
    for (int ui = w; ui < 64; ui += 8) {
        const int enc = UNITS[ui];
        const int R = enc >> 5, C = (enc >> 2) & 7, type = enc & 1;
        const float* blk = blocks + (R * (R + 1) / 2 + C) * BLK_FLOATS;
        if (type == 0) {
            // row-pass: y[32R+l] += sum_c blk[l][c] * v[32C+c]
            const float4* vq = (const float4*)(v + 32 * C);
            const float* bl = blk + l * 32;
            const int lx = l & 7;
            float a0 = 0.f, a1 = 0.f, a2 = 0.f, a3 = 0.f;
#pragma unroll
            for (int q = 0; q < 8; ++q) {
                float4 a = *(const float4*)(bl + ((q ^ lx) << 2));
                float4 vv = vq[q];
                a0 = fmaf(a.x, vv.x, a0);
                a1 = fmaf(a.y, vv.y, a1);
                a2 = fmaf(a.z, vv.z, a2);
                a3 = fmaf(a.w, vv.w, a3);
            }
            myp[32 * R + l] += (a0 + a1) + (a2 + a3);
        } else {
            // col-pass: y[32C+l] += sum_r blk[r][l] * v[32R+r]
            const int hi = l >> 2, lo = l & 3;
            const float* vb = v + 32 * R;
            float a0 = 0.f, a1 = 0.f, a2 = 0.f, a3 = 0.f;
#pragma unroll
            for (int rq = 0; rq < 8; ++rq) {
                float4 vv = *(const float4*)(vb + 4 * rq);
                const float* base = blk + rq * 128;
                a0 = fmaf(base[        (((hi ^ (4 * rq & 7)) << 2) | lo)], vv.x, a0);
                a1 = fmaf(base[32  + (((hi ^ ((4 * rq + 1) & 7)) << 2) | lo)], vv.y, a1);
                a2 = fmaf(base[64  + (((hi ^ ((4 * rq + 2) & 7)) << 2) | lo)], vv.z, a2);
                a3 = fmaf(base[96  + (((hi ^ ((4 * rq + 3) & 7)) << 2) | lo)], vv.w, a3);
            }
            myp[32 * C + l] += (a0 + a1) + (a2 + a3);
        }
    }
    __syncthreads();

    float y = 0.f;
#pragma unroll
    for (int ww = 0; ww < 8; ++ww) y += y2s[ww * Y2S_STRIDE + t];
    return y;
}

__global__ __launch_bounds__(256, 1) void k_eig(float* __restrict__ out) {
    extern __shared__ __align__(16) float sm[];
    float* blocks = sm;                          // 36 * 1024
    float* v   = sm + NBLK * BLK_FLOATS;         // 256
    float* vp  = v + 256;                        // 256
    float* red = vp + 256;                       // 64
    float* y2s = red + 64;                       // 8 * 264

    const int b = blockIdx.x;
    const int t = threadIdx.x;
    const float* Cb = g_C + (size_t)b * DOUT * DOUT;

    // Load 36 blocks; diag blocks mirrored to full. Swizzled store.
    for (int s = 0; s < NBLK; ++s) {
        const int R = SB_R[s], C = SB_C[s];
        float* dst = blocks + s * BLK_FLOATS;
#pragma unroll
        for (int k = 0; k < 4; ++k) {
            int idx = k * 256 + t;
            int r = idx >> 5, c = idx & 31;
            float val;
            if (R > C || c <= r) val = Cb[(32 * R + r) * DOUT + 32 * C + c];
            else                 val = Cb[(32 * C + c) * DOUT + 32 * R + r];
            dst[sw_off(r, c)] = val;
        }
    }
    v[t] = Cb[t * DOUT];   // column 0
    __syncthreads();

    {
        float n2 = blockSum(v[t] * v[t], red, t);
        v[t] *= rsqrtf(fmaxf(n2, 1e-30f));
    }
    __syncthreads();

    // Warm-up power iterations
    for (int it = 0; it < 6; ++it) {
        float s = symMatvecB(blocks, v, y2s, t);
        float n2 = blockSum(s * s, red, t);
        v[t] = s * rsqrtf(fmaxf(n2, 1e-30f));
        __syncthreads();
    }

    // Chebyshev iteration on interval [0, (1-eps)*rho]
    float eps = 0.008f;
    float r2prev = 1e30f;
    for (int outer = 0; outer < 48; ++outer) {
        float s = symMatvecB(blocks, v, y2s, t);
        float rho = blockSum(v[t] * s, red, t);
        float d = s - rho * v[t];
        float r2 = blockSum(d * d, red, t);
        float tol = 4e-6f * rho;
        if (r2 < tol * tol) break;
        if (r2 > 0.3f * r2prev) eps = fmaxf(eps * 0.45f, 3e-4f);
        r2prev = r2;

        const float inv2 = 2.0f / (rho * (1.0f - eps));
        vp[t] = v[t];
        v[t] = inv2 * s - v[t];
        __syncthreads();
        for (int m = 0; m < 16; ++m) {
            float z = symMatvecB(blocks, v, y2s, t);
            float vn = 2.0f * inv2 * z - 2.0f * v[t] - vp[t];
            vp[t] = v[t];
            v[t] = vn;
            __syncthreads();
        }
        float n2 = blockSum(v[t] * v[t], red, t);
        v[t] *= rsqrtf(fmaxf(n2, 1e-30f));
        __syncthreads();
    }

    {
        float n2 = blockSum(v[t] * v[t], red, t);
        v[t] *= (1.0f / sqrtf(fmaxf(n2, 1e-30f)));
        __syncthreads();
    }

    float av = fabsf(v[t]);
    float mx = blockMax(av, red, t);
    int idx = (av == mx) ? t : 256;
    int imin = blockMinInt(idx, red, t);
    if (t == imin) red[40] = (v[t] < 0.0f) ? -1.0f : 1.0f;
    __syncthreads();
    out[b * 256 + t] = v[t] * red[40];
}

// ---------------------------------------------------------------------------
extern "C" void kernel_launch(void* const* d_in, const int* in_sizes, int n_in,
                              void* d_out, int out_size) {
    const float* x = (const float*)d_in[0];
    const float* w = (const float*)d_in[1];
    float* out = (float*)d_out;

    cudaFuncSetAttribute(k_eig, cudaFuncAttributeMaxDynamicSharedMemorySize,
                         EIG_SMEM_BYTES);

    k_u<<<NCAPS, 256>>>(x, w);
    k_syrk<<<dim3(10, BATCH), 64>>>();
    k_eig<<<BATCH, 256, EIG_SMEM_BYTES>>>(out);
}

// round 8
// speedup vs baseline: 1.5330x; 1.0437x over previous
#include <cuda_runtime.h>
#include <cuda_bf16.h>
#include <cstdint>
#include <math.h>

#define BATCH 64
#define NCAPS 2048
#define IDIM 16
#define DOUT 256

typedef unsigned int u32;
typedef unsigned long long u64;

__device__ float g_u[(size_t)BATCH * NCAPS * DOUT];   // 134 MB
__device__ float g_C[(size_t)BATCH * DOUT * DOUT];    // 16 MB (lower triangle valid)

// ---------------------------------------------------------------------------
// Stage 1: u[b,c,o] = sum_i x[b,c,i] * w[c,i,o]
// ---------------------------------------------------------------------------
__global__ void k_u(const float* __restrict__ x, const float* __restrict__ w) {
    const int c = blockIdx.x;
    const int o = threadIdx.x;

    __shared__ __align__(16) float Xs[BATCH * IDIM];

    float W[IDIM];
#pragma unroll
    for (int i = 0; i < IDIM; ++i)
        W[i] = w[((size_t)c * IDIM + i) * DOUT + o];

    for (int l = o; l < BATCH * IDIM; l += 256) {
        int bb = l >> 4, ii = l & 15;
        Xs[l] = x[((size_t)bb * NCAPS + c) * IDIM + ii];
    }
    __syncthreads();

    for (int bb = 0; bb < BATCH; ++bb) {
        const float4 x0 = *(const float4*)&Xs[bb * IDIM + 0];
        const float4 x1 = *(const float4*)&Xs[bb * IDIM + 4];
        const float4 x2 = *(const float4*)&Xs[bb * IDIM + 8];
        const float4 x3 = *(const float4*)&Xs[bb * IDIM + 12];
        float a0 = x0.x * W[0], a1 = x0.y * W[1], a2 = x0.z * W[2], a3 = x0.w * W[3];
        a0 = fmaf(x1.x, W[4], a0);  a1 = fmaf(x1.y, W[5], a1);
        a2 = fmaf(x1.z, W[6], a2);  a3 = fmaf(x1.w, W[7], a3);
        a0 = fmaf(x2.x, W[8], a0);  a1 = fmaf(x2.y, W[9], a1);
        a2 = fmaf(x2.z, W[10], a2); a3 = fmaf(x2.w, W[11], a3);
        a0 = fmaf(x3.x, W[12], a0); a1 = fmaf(x3.y, W[13], a1);
        a2 = fmaf(x3.z, W[14], a2); a3 = fmaf(x3.w, W[15], a3);
        g_u[((size_t)bb * NCAPS + c) * DOUT + o] = (a0 + a1) + (a2 + a3);
    }
}

// ---------------------------------------------------------------------------
// Stage 2: lower-triangle tiles of C_b = U_b^T U_b (FFMA2, cp.async dbuf)
// grid: (10, 64), block: 64  — unchanged
// ---------------------------------------------------------------------------
__device__ __forceinline__ void cp16(u32 saddr, const float* g) {
    asm volatile("cp.async.ca.shared.global [%0], [%1], 16;\n" :: "r"(saddr), "l"(g));
}
__device__ __forceinline__ u64 dupf(float f) {
    u64 r;
    asm("mov.b64 %0, {%1, %1};" : "=l"(r) : "f"(f));
    return r;
}
__device__ __forceinline__ void ffma2(u64& acc, u64 a, u64 b) {
    asm("fma.rn.f32x2 %0, %1, %2, %0;" : "+l"(acc) : "l"(a), "l"(b));
}

__device__ __forceinline__ void sy_load(u32 sA, u32 sB,
                                        const float* Ub, int kc, int buf,
                                        int dbase, int ebase, bool diag, int tid) {
#pragma unroll
    for (int q = 0; q < 4; ++q) {
        int idx = q * 64 + tid;
        int r = idx >> 4;
        int c4 = (idx & 15) << 2;
        const float* srow = Ub + (size_t)(kc + r) * DOUT;
        u32 so = (u32)((buf * 1024 + r * 64 + c4) * 4);
        cp16(sA + so, srow + dbase + c4);
        if (!diag) cp16(sB + so, srow + ebase + c4);
    }
}

__global__ __launch_bounds__(64, 6) void k_syrk() {
    const int p = blockIdx.x;
    const int b = blockIdx.y;

    int dt, et;
    if (p < 1)      { dt = 0; et = 0; }
    else if (p < 3) { dt = 1; et = p - 1; }
    else if (p < 6) { dt = 2; et = p - 3; }
    else            { dt = 3; et = p - 6; }
    const bool diag = (dt == et);

    const int tid = threadIdx.x;
    const int tx = tid & 7, ty = tid >> 3;

    __shared__ __align__(16) float As[2][16][64];
    __shared__ __align__(16) float Bs[2][16][64];

    const float* Ub = g_u + (size_t)b * NCAPS * DOUT;
    const int dbase = dt * 64, ebase = et * 64;

    u64 acc[4][8];
#pragma unroll
    for (int i = 0; i < 4; ++i)
#pragma unroll
        for (int j = 0; j < 8; ++j) acc[i][j] = 0ull;

    u32 sA = (u32)__cvta_generic_to_shared(&As[0][0][0]);
    u32 sB = (u32)__cvta_generic_to_shared(&Bs[0][0][0]);

    sy_load(sA, sB, Ub, 0, 0, dbase, ebase, diag, tid);
    asm volatile("cp.async.commit_group;\n");

    for (int chunk = 0; chunk < NCAPS / 16; ++chunk) {
        const int buf = chunk & 1;
        if (chunk + 1 < NCAPS / 16) {
            sy_load(sA, sB, Ub, (chunk + 1) * 16, buf ^ 1, dbase, ebase, diag, tid);
            asm volatile("cp.async.commit_group;\n");
            asm volatile("cp.async.wait_group 1;\n");
        } else {
            asm volatile("cp.async.wait_group 0;\n");
        }
        __syncthreads();

#pragma unroll
        for (int kk = 0; kk < 16; ++kk) {
            ulonglong2 a01 = *(const ulonglong2*)&As[buf][kk][ty * 8];
            ulonglong2 a23 = *(const ulonglong2*)&As[buf][kk][ty * 8 + 4];
            const float* bp = diag ? &As[buf][kk][tx * 8] : &Bs[buf][kk][tx * 8];
            float4 bl = *(const float4*)bp;
            float4 bh = *(const float4*)(bp + 4);
            u64 bd[8];
            bd[0] = dupf(bl.x); bd[1] = dupf(bl.y); bd[2] = dupf(bl.z); bd[3] = dupf(bl.w);
            bd[4] = dupf(bh.x); bd[5] = dupf(bh.y); bd[6] = dupf(bh.z); bd[7] = dupf(bh.w);
            u64 ap[4] = {a01.x, a01.y, a23.x, a23.y};
#pragma unroll
            for (int ip = 0; ip < 4; ++ip)
#pragma unroll
                for (int j = 0; j < 8; ++j)
                    ffma2(acc[ip][j], ap[ip], bd[j]);
        }
        __syncthreads();
    }

    float* Cb = g_C + (size_t)b * DOUT * DOUT;
#pragma unroll
    for (int ip = 0; ip < 4; ++ip) {
        int d0 = dbase + ty * 8 + 2 * ip;
#pragma unroll
        for (int j = 0; j < 8; ++j) {
            float2 val = *(float2*)&acc[ip][j];
            int e = ebase + tx * 8 + j;
            Cb[d0 * DOUT + e] = val.x;
            Cb[(d0 + 1) * DOUT + e] = val.y;
        }
    }
}

// ---------------------------------------------------------------------------
// Stage 3: top eigenvector via Chebyshev. 512 threads (16 warps), 36 swizzled
// 32x32 blocks, 64 conflict-free pass-units (36 row + 28 col), 4 per warp.
// ---------------------------------------------------------------------------
#define NBLK 36
#define BLK_FLOATS 1024
#define NW 16
#define Y2S_STRIDE 264
#define EIG_SMEM_FLOATS (NBLK * BLK_FLOATS + 2 * 256 + 64 + NW * Y2S_STRIDE)
#define EIG_SMEM_BYTES (EIG_SMEM_FLOATS * 4)

// block s -> (R, C)
__device__ const unsigned char SB_R[NBLK] = {
    0, 1,1, 2,2,2, 3,3,3,3, 4,4,4,4,4, 5,5,5,5,5,5,
    6,6,6,6,6,6,6, 7,7,7,7,7,7,7,7 };
__device__ const unsigned char SB_C[NBLK] = {
    0, 0,1, 0,1,2, 0,1,2,3, 0,1,2,3,4, 0,1,2,3,4,5,
    0,1,2,3,4,5,6, 0,1,2,3,4,5,6,7 };

// pass-units: enc = R*32 + C*4 + type. 36 row-passes then 28 col-passes;
// warp w takes indices {w, w+16, w+32, w+48} -> 2-3 rows + 1-2 cols each.
__device__ const unsigned char UNITS[64] = {
    0, 32, 36, 64, 68, 72, 96, 100, 104, 108, 128, 132, 136, 140, 144, 160,
    164, 168, 172, 176, 180, 192, 196, 200, 204, 208, 212, 216, 224, 228, 232, 236,
    240, 244, 248, 252,
    33, 65, 69, 97, 101, 105, 129, 133, 137, 141, 161, 165, 169, 173, 177, 193,
    197, 201, 205, 209, 213, 225, 229, 233, 237, 241, 245, 249 };

// swizzled offset within a block: element (r, c)
__device__ __forceinline__ int sw_off(int r, int c) {
    return r * 32 + ((((c >> 2) ^ (r & 7)) << 2) | (c & 3));
}

__device__ __forceinline__ float warpSum(float v) {
#pragma unroll
    for (int o = 16; o; o >>= 1) v += __shfl_xor_sync(0xffffffffu, v, o);
    return v;
}
__device__ float blockSum(float val, float* red, int t) {
    val = warpSum(val);
    if ((t & 31) == 0) red[t >> 5] = val;
    __syncthreads();
    if (t < 32) {
        float x = (t < NW) ? red[t] : 0.0f;
        x = warpSum(x);
        if (t == 0) red[32] = x;
    }
    __syncthreads();
    float r = red[32];
    __syncthreads();
    return r;
}
__device__ float blockMax(float val, float* red, int t) {
#pragma unroll
    for (int o = 16; o; o >>= 1) val = fmaxf(val, __shfl_xor_sync(0xffffffffu, val, o));
    if ((t & 31) == 0) red[t >> 5] = val;
    __syncthreads();
    if (t < 32) {
        float x = (t < NW) ? red[t] : -1.0f;
#pragma unroll
        for (int o = 16; o; o >>= 1) x = fmaxf(x, __shfl_xor_sync(0xffffffffu, x, o));
        if (t == 0) red[32] = x;
    }
    __syncthreads();
    float r = red[32];
    __syncthreads();
    return r;
}
__device__ int blockMinInt(int val, float* redf, int t) {
    int* red = (int*)redf;
#pragma unroll
    for (int o = 16; o; o >>= 1) val = min(val, __shfl_xor_sync(0xffffffffu, val, o));
    if ((t & 31) == 0) red[t >> 5] = val;
    __syncthreads();
    if (t < 32) {
        int x = (t < NW) ? red[t] : 0x7fffffff;
#pragma unroll
        for (int o = 16; o; o >>= 1) x = min(x, __shfl_xor_sync(0xffffffffu, x, o));
        if (t == 0) red[32] = x;
    }
    __syncthreads();
    int r = red[32];
    __syncthreads();
    return r;
}

// y[t] = (C v)[t] for t<256. One internal __syncthreads at the end of the
// accumulation phase. Caller must sync after updating v.
__device__ __forceinline__ float symMatvecB(const float* __restrict__ blocks,
                                            const float* __restrict__ v,
                                            float* __restrict__ y2s,
                                            int t) {
    const int l = t & 31, w = t >> 5;   // w in 0..15
    float* myp = y2s + w * Y2S_STRIDE;

#pragma unroll
    for (int k = 0; k < 8; ++k) myp[32 * k + l] = 0.0f;

#pragma unroll
    for (int q = 0; q < 4; ++q) {
        const int enc = UNITS[w + 16 * q];
        const int R = enc >> 5, C = (enc >> 2) & 7, type = enc & 1;
        const float* blk = blocks + (R * (R + 1) / 2 + C) * BLK_FLOATS;
        if (type == 0) {
            // row-pass: y[32R+l] += sum_c blk[l][c] * v[32C+c]
            const float4* vq = (const float4*)(v + 32 * C);
            const float* bl = blk + l * 32;
            const int lx = l & 7;
            float a0 = 0.f, a1 = 0.f, a2 = 0.f, a3 = 0.f;
#pragma unroll
            for (int qq = 0; qq < 8; ++qq) {
                float4 a = *(const float4*)(bl + ((qq ^ lx) << 2));
                float4 vv = vq[qq];
                a0 = fmaf(a.x, vv.x, a0);
                a1 = fmaf(a.y, vv.y, a1);
                a2 = fmaf(a.z, vv.z, a2);
                a3 = fmaf(a.w, vv.w, a3);
            }
            myp[32 * R + l] += (a0 + a1) + (a2 + a3);
        } else {
            // col-pass: y[32C+l] += sum_r blk[r][l] * v[32R+r]
            const int hi = l >> 2, lo = l & 3;
            const float* vb = v + 32 * R;
            float a0 = 0.f, a1 = 0.f, a2 = 0.f, a3 = 0.f;
#pragma unroll
            for (int rq = 0; rq < 8; ++rq) {
                float4 vv = *(const float4*)(vb + 4 * rq);
                const float* base = blk + rq * 128;
                a0 = fmaf(base[       (((hi ^ ((4 * rq)     & 7)) << 2) | lo)], vv.x, a0);
                a1 = fmaf(base[32  + (((hi ^ ((4 * rq + 1) & 7)) << 2) | lo)], vv.y, a1);
                a2 = fmaf(base[64  + (((hi ^ ((4 * rq + 2) & 7)) << 2) | lo)], vv.z, a2);
                a3 = fmaf(base[96  + (((hi ^ ((4 * rq + 3) & 7)) << 2) | lo)], vv.w, a3);
            }
            myp[32 * C + l] += (a0 + a1) + (a2 + a3);
        }
    }
    __syncthreads();

    float y = 0.f;
    if (t < 256) {
#pragma unroll
        for (int ww = 0; ww < NW; ++ww) y += y2s[ww * Y2S_STRIDE + t];
    }
    return y;
}

__global__ __launch_bounds__(512, 1) void k_eig(float* __restrict__ out) {
    extern __shared__ __align__(16) float sm[];
    float* blocks = sm;                          // 36 * 1024
    float* v   = sm + NBLK * BLK_FLOATS;         // 256
    float* vp  = v + 256;                        // 256
    float* red = vp + 256;                       // 64
    float* y2s = red + 64;                       // 16 * 264

    const int b = blockIdx.x;
    const int t = threadIdx.x;
    const bool act = (t < 256);
    const float* Cb = g_C + (size_t)b * DOUT * DOUT;

    // Load 36 blocks; diag blocks mirrored to full. Swizzled store.
    for (int s = 0; s < NBLK; ++s) {
        const int R = SB_R[s], C = SB_C[s];
        float* dst = blocks + s * BLK_FLOATS;
#pragma unroll
        for (int k = 0; k < 2; ++k) {
            int idx = k * 512 + t;
            int r = idx >> 5, c = idx & 31;
            float val;
            if (R > C || c <= r) val = Cb[(32 * R + r) * DOUT + 32 * C + c];
            else                 val = Cb[(32 * C + c) * DOUT + 32 * R + r];
            dst[sw_off(r, c)] = val;
        }
    }
    if (act) v[t] = Cb[t * DOUT];   // column 0
    __syncthreads();

    {
        float n2 = blockSum(act ? v[t] * v[t] : 0.0f, red, t);
        if (act) v[t] *= rsqrtf(fmaxf(n2, 1e-30f));
    }
    __syncthreads();

    // Warm-up power iterations
    for (int it = 0; it < 6; ++it) {
        float s = symMatvecB(blocks, v, y2s, t);
        float n2 = blockSum(s * s, red, t);   // s==0 for t>=256
        if (act) v[t] = s * rsqrtf(fmaxf(n2, 1e-30f));
        __syncthreads();
    }

    // Chebyshev iteration on interval [0, (1-eps)*rho]
    float eps = 0.008f;
    float r2prev = 1e30f;
    for (int outer = 0; outer < 48; ++outer) {
        float s = symMatvecB(blocks, v, y2s, t);
        float rho = blockSum(act ? v[t] * s : 0.0f, red, t);
        float d = act ? (s - rho * v[t]) : 0.0f;
        float r2 = blockSum(d * d, red, t);
        float tol = 4e-6f * rho;
        if (r2 < tol * tol) break;
        if (r2 > 0.3f * r2prev) eps = fmaxf(eps * 0.45f, 3e-4f);
        r2prev = r2;

        const float inv2 = 2.0f / (rho * (1.0f - eps));
        if (act) {
            vp[t] = v[t];
            v[t] = inv2 * s - v[t];
        }
        __syncthreads();
        for (int m = 0; m < 16; ++m) {
            float z = symMatvecB(blocks, v, y2s, t);
            if (act) {
                float vn = 2.0f * inv2 * z - 2.0f * v[t] - vp[t];
                vp[t] = v[t];
                v[t] = vn;
            }
            __syncthreads();
        }
        float n2 = blockSum(act ? v[t] * v[t] : 0.0f, red, t);
        if (act) v[t] *= rsqrtf(fmaxf(n2, 1e-30f));
        __syncthreads();
    }

    {
        float n2 = blockSum(act ? v[t] * v[t] : 0.0f, red, t);
        if (act) v[t] *= (1.0f / sqrtf(fmaxf(n2, 1e-30f)));
        __syncthreads();
    }

    float av = act ? fabsf(v[t]) : -1.0f;
    float mx = blockMax(av, red, t);
    int idx = (act && av == mx) ? t : 1024;
    int imin = blockMinInt(idx, red, t);
    if (t == imin) red[40] = (v[t] < 0.0f) ? -1.0f : 1.0f;
    __syncthreads();
    if (act) out[b * 256 + t] = v[t] * red[40];
}

// ---------------------------------------------------------------------------
extern "C" void kernel_launch(void* const* d_in, const int* in_sizes, int n_in,
                              void* d_out, int out_size) {
    const float* x = (const float*)d_in[0];
    const float* w = (const float*)d_in[1];
    float* out = (float*)d_out;

    cudaFuncSetAttribute(k_eig, cudaFuncAttributeMaxDynamicSharedMemorySize,
                         EIG_SMEM_BYTES);

    k_u<<<NCAPS, 256>>>(x, w);
    k_syrk<<<dim3(10, BATCH), 64>>>();
    k_eig<<<BATCH, 512, EIG_SMEM_BYTES>>>(out);
}